// round 10
// baseline (speedup 1.0000x reference)
#include <cuda_runtime.h>
#include <math.h>

#define BB 256
#define SS 256
#define HH 512
#define INF 512
#define XROW 514   // IN + 2
#define NBLK 128   // persistent recurrence blocks (1/SM, co-resident)
#define KC 64      // k-chunk for staged h
#define NCHUNK (HH / KC)          // 8
#define CB (KC * BB * 4)          // 65536 bytes per h chunk
#define GB_BYTES (8 * BB * 4 * 4) // 32768 bytes of G per block per step

// SMEM partition: ws2 64KB | Abuf 2x64KB | Gs 32KB | mbarriers
#define SM_WS2   0
#define SM_AS    65536
#define SM_GS    (65536 + 131072)
#define SM_MB    (65536 + 131072 + 32768)
#define SM_TOTAL (65536 + 131072 + 32768 + 64)   // 229440

// Scratch (device globals; no runtime allocation allowed)
// G2 layout: [s][hblk:128][g:8][b:256][hq:4] -> per (s,hblk) 32KB contiguous
__device__ __align__(128) float g_G2[(size_t)SS * 128 * 8 * BB * 4];
__device__ __align__(128) float g_hT[2][HH * BB];   // [h][b], ping-pong
__device__ unsigned g_count;                        // barrier ctr, self-resetting

// ---- fast activations (HW MUFU; ~1e-6 err vs 1e-3 tolerance) ----
__device__ __forceinline__ float sigf(float x) {
    return __fdividef(1.0f, 1.0f + __expf(-x));
}
__device__ __forceinline__ float tanh_fast(float x) {
    float a = fabsf(x);
    float e = __expf(-2.0f * a);
    float t = __fdividef(1.0f - e, 1.0f + e);
    return copysignf(t, x);
}

// ---- f32x2 packed-FMA helpers ----
__device__ __forceinline__ unsigned long long pk2(float x, float y) {
    unsigned long long r;
    asm("mov.b64 %0, {%1, %2};" : "=l"(r) : "f"(x), "f"(y));
    return r;
}
__device__ __forceinline__ void fma2(unsigned long long& d, unsigned long long a,
                                     unsigned long long b) {
    asm("fma.rn.f32x2 %0, %1, %2, %0;" : "+l"(d) : "l"(a), "l"(b));
}
__device__ __forceinline__ float2 upk2(unsigned long long v) {
    float2 f;
    asm("mov.b64 {%0, %1}, %2;" : "=f"(f.x), "=f"(f.y) : "l"(v));
    return f;
}

// ---- bulk copy + mbarrier helpers ----
__device__ __forceinline__ unsigned smem_u32(const void* p) {
    return (unsigned)__cvta_generic_to_shared(p);
}
__device__ __forceinline__ void mbar_init(unsigned mbar, unsigned cnt) {
    asm volatile("mbarrier.init.shared.b64 [%0], %1;" :: "r"(mbar), "r"(cnt) : "memory");
}
__device__ __forceinline__ void mbar_expect_tx(unsigned mbar, unsigned bytes) {
    asm volatile("mbarrier.arrive.expect_tx.shared.b64 _, [%0], %1;"
                 :: "r"(mbar), "r"(bytes) : "memory");
}
__device__ __forceinline__ void bulk_g2s(unsigned dst_smem, const void* src,
                                         unsigned bytes, unsigned mbar) {
    asm volatile(
        "cp.async.bulk.shared::cluster.global.mbarrier::complete_tx::bytes "
        "[%0], [%1], %2, [%3];"
        :: "r"(dst_smem), "l"(src), "r"(bytes), "r"(mbar) : "memory");
}
__device__ __forceinline__ void mbar_wait(unsigned mbar, unsigned parity) {
    asm volatile(
        "{\n\t.reg .pred P;\n\t"
        "WL_%=:\n\t"
        "mbarrier.try_wait.parity.acquire.cta.shared::cta.b64 P, [%0], %1, 0x989680;\n\t"
        "@P bra WD_%=;\n\t"
        "bra.uni WL_%=;\n\t"
        "WD_%=:\n\t}"
        :: "r"(mbar), "r"(parity) : "memory");
}
__device__ __forceinline__ unsigned ld_cg_u32(const unsigned* p) {
    unsigned v;
    asm volatile("ld.global.cg.u32 %0, [%1];" : "=r"(v) : "l"(p));
    return v;
}

struct ProjArgs {
    const float* x;
    const float* Wx[8];
    const float* bias[8];
    const float* aux1[8];
    const float* aux2[8];
};

// ---------------------------------------------------------------------------
// Projection GEMM — R3's measured-best mainloop verbatim; epilogue stores to
// the rec-friendly G2 layout (one float4 per (m,g,h-quad)).
// ---------------------------------------------------------------------------
__global__ void proj_kernel(ProjArgs p) {
    const int g  = blockIdx.z;
    const int m0 = blockIdx.y * 64;
    const int n0 = blockIdx.x * 64;

    __shared__ float As[64][17];
    __shared__ __align__(16) float Bs[16][64];

    const int tid = threadIdx.x;
    const int tm = tid >> 4;
    const int tn = tid & 15;

    const float* W = p.Wx[g];

    unsigned long long acc2[4][2];
    #pragma unroll
    for (int i = 0; i < 4; i++) { acc2[i][0] = 0ULL; acc2[i][1] = 0ULL; }

    for (int k0 = 0; k0 < INF; k0 += 16) {
        #pragma unroll
        for (int q = 0; q < 4; q++) {
            int m = q * 16 + (tid >> 4);
            int kk = tid & 15;
            As[m][kk] = p.x[(size_t)(m0 + m) * XROW + 2 + k0 + kk];
        }
        {
            int idx = tid * 4;
            int kk = idx >> 6;
            int hc = idx & 63;
            float4 w = *(const float4*)&W[(size_t)(k0 + kk) * HH + n0 + hc];
            *(float4*)&Bs[kk][hc] = w;
        }
        __syncthreads();

        #pragma unroll
        for (int kk = 0; kk < 16; kk++) {
            ulonglong2 bq = *(const ulonglong2*)&Bs[kk][tn * 4];
            #pragma unroll
            for (int i = 0; i < 4; i++) {
                float a = As[tm * 4 + i][kk];
                unsigned long long a2 = pk2(a, a);
                fma2(acc2[i][0], a2, bq.x);
                fma2(acc2[i][1], a2, bq.y);
            }
        }
        __syncthreads();
    }

    const float* bias = p.bias[g];
    const float* a1p = p.aux1[g];
    const float* a2p = p.aux2[g];

    float4 bias4 = *(const float4*)&bias[n0 + tn * 4];
    float4 a14 = make_float4(0.f, 0.f, 0.f, 0.f);
    float4 a24 = make_float4(0.f, 0.f, 0.f, 0.f);
    if (g >= 3) a14 = *(const float4*)&a1p[n0 + tn * 4];
    if (g == 7) a24 = *(const float4*)&a2p[n0 + tn * 4];

    const int hb = (n0 >> 2) + tn;    // h-quad index 0..127

    #pragma unroll
    for (int i = 0; i < 4; i++) {
        int m = m0 + tm * 4 + i;
        int bidx = m / SS;
        int sidx = m % SS;
        float Tt = p.x[(size_t)m * XROW + 0];
        float Dt = p.x[(size_t)m * XROW + 1];
        float2 lo = upk2(acc2[i][0]);
        float2 hi = upk2(acc2[i][1]);
        float4 v = make_float4(lo.x + bias4.x, lo.y + bias4.y,
                               hi.x + bias4.z, hi.y + bias4.w);
        if (g == 3 || g == 4) {
            v.x += sigf(Tt * a14.x); v.y += sigf(Tt * a14.y);
            v.z += sigf(Tt * a14.z); v.w += sigf(Tt * a14.w);
        } else if (g == 5 || g == 6) {
            v.x += sigf(Dt * a14.x); v.y += sigf(Dt * a14.y);
            v.z += sigf(Dt * a14.z); v.w += sigf(Dt * a14.w);
        } else if (g == 7) {
            v.x += Tt * a14.x + Dt * a24.x; v.y += Tt * a14.y + Dt * a24.y;
            v.z += Tt * a14.z + Dt * a24.z; v.w += Tt * a14.w + Dt * a24.w;
        }
        size_t base2 = (((size_t)sidx * 128 + hb) * 8 + g) * ((size_t)BB * 4)
                     + (size_t)bidx * 4;
        *(float4*)&g_G2[base2] = v;
    }
}

// ---------------------------------------------------------------------------
// Persistent recurrence. 128 blocks x 256 thr (R3 mapping: thread = 4b x 1h
// x 4 gates). h and G arrive via cp.async.bulk (UBLKCP) + mbarrier — the
// R3-R9 versions issued ~35K LDGSTS/SM/step (rt=8/SMSP => ~39us/step of pure
// issue); now it's 9 bulk instructions/step.
// ---------------------------------------------------------------------------
__global__ void __launch_bounds__(256, 1)
rec_kernel(const float* __restrict__ Whi, const float* __restrict__ Whf,
           const float* __restrict__ Whc, const float* __restrict__ Who,
           float* __restrict__ out, unsigned long long out_size) {
    extern __shared__ __align__(16) char smem_raw[];
    unsigned long long* ws2 = (unsigned long long*)(smem_raw + SM_WS2); // [k*16+hc*4+g]
    float* Abuf = (float*)(smem_raw + SM_AS);                           // 2 x [KC][256]
    float* Gs   = (float*)(smem_raw + SM_GS);                           // [g][b][4h]
    const unsigned mb0 = smem_u32(smem_raw + SM_MB);
    const unsigned mb1 = smem_u32(smem_raw + SM_MB + 8);
    const unsigned mbG = smem_u32(smem_raw + SM_MB + 16);
    const unsigned GsAddr = smem_u32(Gs);
    const unsigned AbAddr = smem_u32(Abuf);

    const int tid = threadIdx.x;
    const int h0 = blockIdx.x * 4;
    const int hg = tid & 3;
    const int b0 = (tid >> 2) * 4;

    // Preload duplicated weight pairs: ws2[k*16 + hc*4 + g] = (w,w)
    {
        const float* Wg[4] = {Whi, Whf, Whc, Who};
        for (int idx = tid; idx < HH * 16; idx += 256) {
            int k = idx >> 4, hc = (idx >> 2) & 3, g = idx & 3;
            float w = __ldg(&Wg[g][(size_t)k * HH + h0 + hc]);
            ws2[idx] = pk2(w, w);
        }
    }
    if (tid == 0) {
        mbar_init(mb0, 1);
        mbar_init(mb1, 1);
        mbar_init(mbG, 1);
        asm volatile("fence.proxy.async;" ::: "memory");
    }
    __syncthreads();

    int phA0 = 0, phA1 = 0, phG = 0;
    float cst[4] = {0.f, 0.f, 0.f, 0.f};

    for (int t = 0; t < SS; t++) {
        const float* hT = g_hT[t & 1];
        float* hTn = g_hT[(t + 1) & 1];

        if (tid == 0) {
            // G for this step: one contiguous 32KB block
            const float* gsrc = g_G2 + ((size_t)t * 128 + blockIdx.x) * (8 * BB * 4);
            mbar_expect_tx(mbG, GB_BYTES);
            bulk_g2s(GsAddr, gsrc, GB_BYTES, mbG);
            if (t > 0) {   // prime h chunks 0,1
                mbar_expect_tx(mb0, CB);
                bulk_g2s(AbAddr, hT, CB, mb0);
                mbar_expect_tx(mb1, CB);
                bulk_g2s(AbAddr + CB, (const char*)hT + CB, CB, mb1);
            }
        }

        unsigned long long acc[2][4];
        #pragma unroll
        for (int rp = 0; rp < 2; rp++)
            #pragma unroll
            for (int g = 0; g < 4; g++) acc[rp][g] = 0ULL;

        if (t > 0) {   // h == 0 at t == 0 -> skip GEMM entirely
            for (int c = 0; c < NCHUNK; c++) {
                if ((c & 1) == 0) { mbar_wait(mb0, phA0); phA0 ^= 1; }
                else              { mbar_wait(mb1, phA1); phA1 ^= 1; }

                const float* A = Abuf + (size_t)(c & 1) * (KC * 256) + b0;
                const unsigned long long* wp = ws2 + (size_t)c * KC * 16 + hg * 4;
                #pragma unroll 8
                for (int k = 0; k < KC; k++) {
                    ulonglong2 aq  = *(const ulonglong2*)(A + k * 256);
                    ulonglong2 w01 = *(const ulonglong2*)(wp + k * 16);
                    ulonglong2 w23 = *(const ulonglong2*)(wp + k * 16 + 2);
                    fma2(acc[0][0], aq.x, w01.x); fma2(acc[1][0], aq.y, w01.x);
                    fma2(acc[0][1], aq.x, w01.y); fma2(acc[1][1], aq.y, w01.y);
                    fma2(acc[0][2], aq.x, w23.x); fma2(acc[1][2], aq.y, w23.x);
                    fma2(acc[0][3], aq.x, w23.y); fma2(acc[1][3], aq.y, w23.y);
                }
                __syncthreads();   // all readers done with this buffer
                if (tid == 0 && c + 2 < NCHUNK) {
                    unsigned mb = (c & 1) ? mb1 : mb0;
                    mbar_expect_tx(mb, CB);
                    bulk_g2s(AbAddr + (c & 1) * CB,
                             (const char*)hT + (size_t)(c + 2) * CB, CB, mb);
                }
            }
        }

        mbar_wait(mbG, phG); phG ^= 1;

        float y[4][4];
        #pragma unroll
        for (int g = 0; g < 4; g++) {
            float2 lo = upk2(acc[0][g]);
            float2 hi = upk2(acc[1][g]);
            y[g][0] = lo.x; y[g][1] = lo.y; y[g][2] = hi.x; y[g][3] = hi.y;
        }

        float hn[4];
        #pragma unroll
        for (int r = 0; r < 4; r++) {
            int b = b0 + r;
            float xi = Gs[(0 * 256 + b) * 4 + hg] + y[0][r];
            float xf = Gs[(1 * 256 + b) * 4 + hg] + y[1][r];
            float xc = Gs[(2 * 256 + b) * 4 + hg] + y[2][r];
            float t1 = Gs[(3 * 256 + b) * 4 + hg];
            float t2 = Gs[(4 * 256 + b) * 4 + hg];
            float d1 = Gs[(5 * 256 + b) * 4 + hg];
            float d2 = Gs[(6 * 256 + b) * 4 + hg];
            float o  = Gs[(7 * 256 + b) * 4 + hg] + y[3][r];

            float it = sigf(xi);
            float ft = sigf(xf);
            float jj = tanh_fast(xc);
            float T1 = sigf(t1), T2 = sigf(t2), D1 = sigf(d1), D2 = sigf(d2);
            float fc = ft * cst[r];
            float ij = it * jj;
            float chat = fc + ij * T1 * D1;
            float cnew = fc + ij * T2 * D2;
            float ot = sigf(o);
            hn[r] = ot * tanh_fast(chat);
            cst[r] = cnew;
        }

        // next-step hidden state: [h][b] layout, float4 over b
        *(float4*)&hTn[(h0 + hg) * BB + b0] = make_float4(hn[0], hn[1], hn[2], hn[3]);

        // stage hn (and c at last step) so each thread emits ONE STG.128
        float* hs = Abuf;          // buffers idle here; reissued only next step
        float* cs = Abuf + 4096;
        #pragma unroll
        for (int r = 0; r < 4; r++) hs[(b0 + r) * 4 + hg] = hn[r];
        if (t == SS - 1) {
            #pragma unroll
            for (int r = 0; r < 4; r++) cs[(b0 + r) * 4 + hg] = cst[r];
        }
        __syncthreads();
        {
            float4 v = *(const float4*)&hs[tid * 4];
            *(float4*)&out[((size_t)tid * SS + t) * HH + h0] = v;
            if (t == SS - 1) {
                unsigned long long base = (unsigned long long)BB * SS * HH;
                unsigned long long o1 = base + (unsigned long long)tid * HH + h0;
                unsigned long long o2 = o1 + (unsigned long long)BB * HH;
                if (o1 + 4 <= out_size) *(float4*)&out[o1] = v;
                if (o2 + 4 <= out_size) *(float4*)&out[o2] = *(const float4*)&cs[tid * 4];
            }
        }

        if (t < SS - 1) {
            // grid barrier: single elected fence/atomic; proxy fence orders the
            // generic smem staging writes before next step's async bulk writes.
            __syncthreads();
            if (tid == 0) {
                __threadfence();
                atomicAdd(&g_count, 1u);
                unsigned target = (unsigned)(t + 1) * (unsigned)NBLK;
                while (ld_cg_u32(&g_count) < target) { __nanosleep(20); }
                __threadfence();
                asm volatile("fence.proxy.async;" ::: "memory");
            }
            __syncthreads();
        }
    }

    // Self-resetting counter for deterministic graph replays
    if (tid == 0) {
        unsigned old = atomicAdd(&g_count, 1u);
        if (old == (unsigned)(SS * NBLK - 1)) atomicExch(&g_count, 0u);
    }
}

extern "C" void kernel_launch(void* const* d_in, const int* in_sizes, int n_in,
                              void* d_out, int out_size) {
    const float* x = (const float*)d_in[0];

    ProjArgs pa = {};
    pa.x = x;
    pa.Wx[0] = (const float*)d_in[1];  pa.bias[0] = (const float*)d_in[3];
    pa.Wx[1] = (const float*)d_in[4];  pa.bias[1] = (const float*)d_in[6];
    pa.Wx[2] = (const float*)d_in[7];  pa.bias[2] = (const float*)d_in[9];
    pa.Wx[3] = (const float*)d_in[10]; pa.aux1[3] = (const float*)d_in[11]; pa.bias[3] = (const float*)d_in[12];
    pa.Wx[4] = (const float*)d_in[13]; pa.aux1[4] = (const float*)d_in[14]; pa.bias[4] = (const float*)d_in[15];
    pa.Wx[5] = (const float*)d_in[16]; pa.aux1[5] = (const float*)d_in[17]; pa.bias[5] = (const float*)d_in[18];
    pa.Wx[6] = (const float*)d_in[19]; pa.aux1[6] = (const float*)d_in[20]; pa.bias[6] = (const float*)d_in[21];
    pa.Wx[7] = (const float*)d_in[22]; pa.aux1[7] = (const float*)d_in[24]; pa.aux2[7] = (const float*)d_in[25];
    pa.bias[7] = (const float*)d_in[26];

    const float* Whi = (const float*)d_in[2];
    const float* Whf = (const float*)d_in[5];
    const float* Whc = (const float*)d_in[8];
    const float* Who = (const float*)d_in[23];

    float* out = (float*)d_out;

    cudaFuncSetAttribute(rec_kernel, cudaFuncAttributeMaxDynamicSharedMemorySize,
                         SM_TOTAL);

    dim3 pgrid(HH / 64, (BB * SS) / 64, 8);
    proj_kernel<<<pgrid, 256>>>(pa);

    rec_kernel<<<NBLK, 256, SM_TOTAL>>>(Whi, Whf, Whc, Who, out,
                                        (unsigned long long)out_size);
}

// round 11
// speedup vs baseline: 1.5358x; 1.5358x over previous
#include <cuda_runtime.h>
#include <math.h>

#define BB 256
#define SS 256
#define HH 512
#define INF 512
#define XROW 514   // IN + 2
#define NBLK 128   // persistent recurrence blocks (1/SM, co-resident)
#define KC 64      // k-chunk for staged h
#define NCHUNK (HH / KC)   // 8
#define NGRP 8
#define GRPSZ 16

// SMEM partition for rec kernel: ws2 64KB | As 2x64KB | Gs 32KB = 224KB
#define SM_WS2   0
#define SM_AS    65536
#define SM_GS    (65536 + 131072)
#define SM_TOTAL (65536 + 131072 + 32768)   // 229376

// Scratch (device globals; no runtime allocation allowed)
__device__ __align__(128) float g_G[(size_t)SS * 8 * BB * HH]; // [s][gate][b][h]
__device__ __align__(128) float g_hT[2][HH * BB];              // [h][b], ping-pong
// Hierarchical barrier state: per-group counters on separate 128B lines,
// a super counter, a broadcast flag (read-only for pollers), and a done ctr.
__device__ __align__(128) unsigned g_cnt[NGRP * 32];           // [g*32]
__device__ __align__(128) unsigned g_cnt2;
__device__ __align__(128) unsigned g_flag;
__device__ __align__(128) unsigned g_done;

// ---- fast activations (HW MUFU; ~1e-6 err vs 1e-3 tolerance) ----
__device__ __forceinline__ float sigf(float x) {
    return __fdividef(1.0f, 1.0f + __expf(-x));
}
__device__ __forceinline__ float tanh_fast(float x) {
    float a = fabsf(x);
    float e = __expf(-2.0f * a);
    float t = __fdividef(1.0f - e, 1.0f + e);
    return copysignf(t, x);
}

// ---- f32x2 packed-FMA helpers ----
__device__ __forceinline__ unsigned long long pk2(float x, float y) {
    unsigned long long r;
    asm("mov.b64 %0, {%1, %2};" : "=l"(r) : "f"(x), "f"(y));
    return r;
}
__device__ __forceinline__ void fma2(unsigned long long& d, unsigned long long a,
                                     unsigned long long b) {
    asm("fma.rn.f32x2 %0, %1, %2, %0;" : "+l"(d) : "l"(a), "l"(b));
}
__device__ __forceinline__ float2 upk2(unsigned long long v) {
    float2 f;
    asm("mov.b64 {%0, %1}, %2;" : "=f"(f.x), "=f"(f.y) : "l"(v));
    return f;
}

// ---- cp.async helpers (cg = L2-only, bypasses stale L1) ----
__device__ __forceinline__ void cpa16(void* dst_smem, const void* src) {
    unsigned d = (unsigned)__cvta_generic_to_shared(dst_smem);
    asm volatile("cp.async.cg.shared.global [%0], [%1], 16;" :: "r"(d), "l"(src));
}
#define CP_COMMIT() asm volatile("cp.async.commit_group;" ::: "memory")
#define CP_WAIT(n)  asm volatile("cp.async.wait_group %0;" :: "n"(n) : "memory")

__device__ __forceinline__ unsigned ld_cg_u32(const unsigned* p) {
    unsigned v;
    asm volatile("ld.global.cg.u32 %0, [%1];" : "=r"(v) : "l"(p));
    return v;
}

struct ProjArgs {
    const float* x;
    const float* Wx[8];
    const float* bias[8];
    const float* aux1[8];
    const float* aux2[8];
};

// ---------------------------------------------------------------------------
// Projection GEMM — R3's measured-best version, verbatim.
// grid = (8, 1024, 8 gates), block = 256. 64x64 tile, 4m x 4n per thread.
// ---------------------------------------------------------------------------
__global__ void proj_kernel(ProjArgs p) {
    const int g  = blockIdx.z;
    const int m0 = blockIdx.y * 64;
    const int n0 = blockIdx.x * 64;

    __shared__ float As[64][17];
    __shared__ __align__(16) float Bs[16][64];

    const int tid = threadIdx.x;
    const int tm = tid >> 4;
    const int tn = tid & 15;

    const float* W = p.Wx[g];

    unsigned long long acc2[4][2];
    #pragma unroll
    for (int i = 0; i < 4; i++) { acc2[i][0] = 0ULL; acc2[i][1] = 0ULL; }

    for (int k0 = 0; k0 < INF; k0 += 16) {
        #pragma unroll
        for (int q = 0; q < 4; q++) {
            int m = q * 16 + (tid >> 4);
            int kk = tid & 15;
            As[m][kk] = p.x[(size_t)(m0 + m) * XROW + 2 + k0 + kk];
        }
        {
            int idx = tid * 4;
            int kk = idx >> 6;
            int hc = idx & 63;
            float4 w = *(const float4*)&W[(size_t)(k0 + kk) * HH + n0 + hc];
            *(float4*)&Bs[kk][hc] = w;
        }
        __syncthreads();

        #pragma unroll
        for (int kk = 0; kk < 16; kk++) {
            ulonglong2 bq = *(const ulonglong2*)&Bs[kk][tn * 4];
            #pragma unroll
            for (int i = 0; i < 4; i++) {
                float a = As[tm * 4 + i][kk];
                unsigned long long a2 = pk2(a, a);
                fma2(acc2[i][0], a2, bq.x);
                fma2(acc2[i][1], a2, bq.y);
            }
        }
        __syncthreads();
    }

    const float* bias = p.bias[g];
    const float* a1p = p.aux1[g];
    const float* a2p = p.aux2[g];

    #pragma unroll
    for (int i = 0; i < 4; i++) {
        int m = m0 + tm * 4 + i;
        int bidx = m / SS;
        int sidx = m % SS;
        float Tt = p.x[(size_t)m * XROW + 0];
        float Dt = p.x[(size_t)m * XROW + 1];
        size_t base = (((size_t)sidx * 8 + g) * BB + bidx) * HH;
        float2 lo = upk2(acc2[i][0]);
        float2 hi = upk2(acc2[i][1]);
        float av[4] = {lo.x, lo.y, hi.x, hi.y};
        #pragma unroll
        for (int j = 0; j < 4; j++) {
            int h = n0 + tn * 4 + j;
            float v = av[j] + bias[h];
            if (g == 3 || g == 4)       v += sigf(Tt * a1p[h]);
            else if (g == 5 || g == 6)  v += sigf(Dt * a1p[h]);
            else if (g == 7)            v += Tt * a1p[h] + Dt * a2p[h];
            g_G[base + h] = v;
        }
    }
}

// ---------------------------------------------------------------------------
// Persistent recurrence — R3's measured-best body (256 thr, KC=64, 2 buffers,
// thread = 4b x 1h x 4g) + t0-skip + fast-MUFU epilogue. The ONE structural
// change this round: hierarchical-arrival + broadcast-flag grid barrier
// (replacing 128-way atomic contention on a single polled line), with
// arrive-early / wait-late so out-stores overlap other blocks' arrivals.
// ---------------------------------------------------------------------------
__global__ void __launch_bounds__(256, 1)
rec_kernel(const float* __restrict__ Whi, const float* __restrict__ Whf,
           const float* __restrict__ Whc, const float* __restrict__ Who,
           float* __restrict__ out, unsigned long long out_size) {
    extern __shared__ __align__(16) char smem_raw[];
    unsigned long long* ws2 = (unsigned long long*)(smem_raw + SM_WS2); // [k*16+hc*4+g]
    float* Asmem = (float*)(smem_raw + SM_AS);                          // 2 x [KC][256]
    float* Gs    = (float*)(smem_raw + SM_GS);                          // [g][b][4h]

    const int tid = threadIdx.x;
    const int h0 = blockIdx.x * 4;
    const int hg = tid & 3;
    const int b0 = (tid >> 2) * 4;
    const int grp = blockIdx.x >> 4;          // 8 groups of 16 blocks

    // Preload duplicated weight pairs: ws2[k*16 + hc*4 + g] = (w,w)
    {
        const float* Wg[4] = {Whi, Whf, Whc, Who};
        for (int idx = tid; idx < HH * 16; idx += 256) {
            int k = idx >> 4, hc = (idx >> 2) & 3, g = idx & 3;
            float w = __ldg(&Wg[g][(size_t)k * HH + h0 + hc]);
            ws2[idx] = pk2(w, w);
        }
    }
    __syncthreads();

    float cst[4] = {0.f, 0.f, 0.f, 0.f};

    for (int t = 0; t < SS; t++) {
        const float* hT = g_hT[t & 1];
        float* hTn = g_hT[(t + 1) & 1];

        if (t > 0) {   // chunk 0 of h (h == 0 at t == 0 -> skip GEMM entirely)
            const char* src = (const char*)hT;
            #pragma unroll
            for (int i = 0; i < 16; i++) {
                int off = (i * 256 + tid) * 16;
                cpa16((char*)Asmem + off, src + off);
            }
            CP_COMMIT();
        }
        // G slices [t][g][b=tid][h0..h0+3]
        {
            #pragma unroll
            for (int g = 0; g < 8; g++) {
                const float* srcg = g_G + (((size_t)t * 8 + g) * BB + tid) * HH + h0;
                cpa16(Gs + (g * 256 + tid) * 4, srcg);
            }
            CP_COMMIT();
        }

        unsigned long long acc[2][4];
        #pragma unroll
        for (int rp = 0; rp < 2; rp++)
            #pragma unroll
            for (int g = 0; g < 4; g++) acc[rp][g] = 0ULL;

        if (t > 0) {
            for (int c = 0; c < NCHUNK; c++) {
                if (c < NCHUNK - 1) {
                    const char* src = (const char*)hT + (size_t)(c + 1) * (KC * 256 * 4);
                    char* dst = (char*)Asmem + (size_t)((c + 1) & 1) * (KC * 256 * 4);
                    #pragma unroll
                    for (int i = 0; i < 16; i++) {
                        int off = (i * 256 + tid) * 16;
                        cpa16(dst + off, src + off);
                    }
                    CP_COMMIT();
                }
                if (c == 0)                 CP_WAIT(2);
                else if (c < NCHUNK - 1)    CP_WAIT(1);
                else                        CP_WAIT(0);
                __syncthreads();

                const float* A = Asmem + (size_t)(c & 1) * (KC * 256) + b0;
                const unsigned long long* wp = ws2 + (size_t)c * KC * 16 + hg * 4;
                #pragma unroll 8
                for (int k = 0; k < KC; k++) {
                    ulonglong2 aq  = *(const ulonglong2*)(A + k * 256);
                    ulonglong2 w01 = *(const ulonglong2*)(wp + k * 16);
                    ulonglong2 w23 = *(const ulonglong2*)(wp + k * 16 + 2);
                    fma2(acc[0][0], aq.x, w01.x); fma2(acc[1][0], aq.y, w01.x);
                    fma2(acc[0][1], aq.x, w01.y); fma2(acc[1][1], aq.y, w01.y);
                    fma2(acc[0][2], aq.x, w23.x); fma2(acc[1][2], aq.y, w23.x);
                    fma2(acc[0][3], aq.x, w23.y); fma2(acc[1][3], aq.y, w23.y);
                }
                __syncthreads();
            }
        } else {
            CP_WAIT(0);
            __syncthreads();
        }

        float y[4][4];
        #pragma unroll
        for (int g = 0; g < 4; g++) {
            float2 lo = upk2(acc[0][g]);
            float2 hi = upk2(acc[1][g]);
            y[g][0] = lo.x; y[g][1] = lo.y; y[g][2] = hi.x; y[g][3] = hi.y;
        }

        float hn[4];
        #pragma unroll
        for (int r = 0; r < 4; r++) {
            int b = b0 + r;
            float xi = Gs[(0 * 256 + b) * 4 + hg] + y[0][r];
            float xf = Gs[(1 * 256 + b) * 4 + hg] + y[1][r];
            float xc = Gs[(2 * 256 + b) * 4 + hg] + y[2][r];
            float t1 = Gs[(3 * 256 + b) * 4 + hg];
            float t2 = Gs[(4 * 256 + b) * 4 + hg];
            float d1 = Gs[(5 * 256 + b) * 4 + hg];
            float d2 = Gs[(6 * 256 + b) * 4 + hg];
            float o  = Gs[(7 * 256 + b) * 4 + hg] + y[3][r];

            float it = sigf(xi);
            float ft = sigf(xf);
            float jj = tanh_fast(xc);
            float T1 = sigf(t1), T2 = sigf(t2), D1 = sigf(d1), D2 = sigf(d2);
            float fc = ft * cst[r];
            float ij = it * jj;
            float chat = fc + ij * T1 * D1;
            float cnew = fc + ij * T2 * D2;
            float ot = sigf(o);
            hn[r] = ot * tanh_fast(chat);
            cst[r] = cnew;
        }

        // next-step hidden state: [h][b] layout, float4 over b
        *(float4*)&hTn[(h0 + hg) * BB + b0] = make_float4(hn[0], hn[1], hn[2], hn[3]);

        // stage hn (and c at last step) so each thread emits ONE STG.128
        float* hs = Asmem;
        float* cs = Asmem + 4096;
        #pragma unroll
        for (int r = 0; r < 4; r++) hs[(b0 + r) * 4 + hg] = hn[r];
        if (t == SS - 1) {
            #pragma unroll
            for (int r = 0; r < 4; r++) cs[(b0 + r) * 4 + hg] = cst[r];
        }
        __syncthreads();   // block-wide join: hTn stores + staging complete

        // ---- ARRIVE EARLY: release this block's hTn stores, then overlap
        // the DRAM out-stores with other blocks' arrivals. ----
        if (t < SS - 1 && tid == 0) {
            __threadfence();
            unsigned old = atomicAdd(&g_cnt[grp * 32], 1u);
            if (old == (unsigned)(GRPSZ * (t + 1) - 1)) {
                unsigned o2 = atomicAdd(&g_cnt2, 1u);
                if (o2 == (unsigned)(NGRP * (t + 1) - 1)) {
                    atomicExch(&g_flag, (unsigned)(t + 1));   // broadcast flag
                }
            }
        }

        {
            float4 v = *(const float4*)&hs[tid * 4];
            *(float4*)&out[((size_t)tid * SS + t) * HH + h0] = v;
            if (t == SS - 1) {
                unsigned long long base = (unsigned long long)BB * SS * HH;
                unsigned long long o1 = base + (unsigned long long)tid * HH + h0;
                unsigned long long o2 = o1 + (unsigned long long)BB * HH;
                if (o1 + 4 <= out_size) *(float4*)&out[o1] = v;
                if (o2 + 4 <= out_size) *(float4*)&out[o2] = *(const float4*)&cs[tid * 4];
            }
        }

        // ---- WAIT LATE: poll the read-only flag line (no atomic ping-pong) ----
        if (t < SS - 1) {
            if (tid == 0) {
                while (ld_cg_u32(&g_flag) < (unsigned)(t + 1)) { __nanosleep(32); }
                __threadfence();
            }
            __syncthreads();
        }
    }

    // Reset barrier state after ALL blocks finish (deterministic graph replays)
    if (tid == 0) {
        unsigned old = atomicAdd(&g_done, 1u);
        if (old == (unsigned)(NBLK - 1)) {
            for (int i = 0; i < NGRP; i++) atomicExch(&g_cnt[i * 32], 0u);
            atomicExch(&g_cnt2, 0u);
            atomicExch(&g_flag, 0u);
            __threadfence();
            atomicExch(&g_done, 0u);
        }
    }
}

extern "C" void kernel_launch(void* const* d_in, const int* in_sizes, int n_in,
                              void* d_out, int out_size) {
    const float* x = (const float*)d_in[0];

    ProjArgs pa = {};
    pa.x = x;
    pa.Wx[0] = (const float*)d_in[1];  pa.bias[0] = (const float*)d_in[3];
    pa.Wx[1] = (const float*)d_in[4];  pa.bias[1] = (const float*)d_in[6];
    pa.Wx[2] = (const float*)d_in[7];  pa.bias[2] = (const float*)d_in[9];
    pa.Wx[3] = (const float*)d_in[10]; pa.aux1[3] = (const float*)d_in[11]; pa.bias[3] = (const float*)d_in[12];
    pa.Wx[4] = (const float*)d_in[13]; pa.aux1[4] = (const float*)d_in[14]; pa.bias[4] = (const float*)d_in[15];
    pa.Wx[5] = (const float*)d_in[16]; pa.aux1[5] = (const float*)d_in[17]; pa.bias[5] = (const float*)d_in[18];
    pa.Wx[6] = (const float*)d_in[19]; pa.aux1[6] = (const float*)d_in[20]; pa.bias[6] = (const float*)d_in[21];
    pa.Wx[7] = (const float*)d_in[22]; pa.aux1[7] = (const float*)d_in[24]; pa.aux2[7] = (const float*)d_in[25];
    pa.bias[7] = (const float*)d_in[26];

    const float* Whi = (const float*)d_in[2];
    const float* Whf = (const float*)d_in[5];
    const float* Whc = (const float*)d_in[8];
    const float* Who = (const float*)d_in[23];

    float* out = (float*)d_out;

    cudaFuncSetAttribute(rec_kernel, cudaFuncAttributeMaxDynamicSharedMemorySize,
                         SM_TOTAL);

    dim3 pgrid(HH / 64, (BB * SS) / 64, 8);
    proj_kernel<<<pgrid, 256>>>(pa);

    rec_kernel<<<NBLK, 256, SM_TOTAL>>>(Whi, Whf, Whc, Who, out,
                                        (unsigned long long)out_size);
}